// round 13
// baseline (speedup 1.0000x reference)
#include <cuda_runtime.h>
#include <cstdint>

// Problem constants
#define PB   64
#define PS   1024
#define PF   768
#define PH   12
#define PP2  64
#define HEADSZ 4096
#define QKVSTRIDE (PB * PH * HEADSZ)   // 3,145,728

__device__ float g_qkv[3LL * QKVSTRIDE];
__device__ float g_o[4096LL * PF];

// ---------------------------------------------------------------------------
// PTX helpers
// ---------------------------------------------------------------------------
__device__ __forceinline__ void cp16(void* s, const void* g) {
    unsigned sa = (unsigned)__cvta_generic_to_shared(s);
    asm volatile("cp.async.cg.shared.global [%0], [%1], 16;\n" :: "r"(sa), "l"(g));
}
__device__ __forceinline__ void cp_commit() { asm volatile("cp.async.commit_group;\n"); }
template <int N>
__device__ __forceinline__ void cp_wait() { asm volatile("cp.async.wait_group %0;\n" :: "n"(N)); }

__device__ __forceinline__ void mma_tf32(float* c, const unsigned* a, const unsigned* b) {
    asm volatile(
        "mma.sync.aligned.m16n8k8.row.col.f32.tf32.tf32.f32 "
        "{%0,%1,%2,%3}, {%4,%5,%6,%7}, {%8,%9}, {%0,%1,%2,%3};"
        : "+f"(c[0]), "+f"(c[1]), "+f"(c[2]), "+f"(c[3])
        : "r"(a[0]), "r"(a[1]), "r"(a[2]), "r"(a[3]), "r"(b[0]), "r"(b[1]));
}

// ldmatrix x4 on 32-bit data viewed as b16 pairs: thread gets one fp32/matrix.
__device__ __forceinline__ void ldsm4(unsigned* r, unsigned saddr) {
    asm volatile("ldmatrix.sync.aligned.m8n8.x4.shared.b16 {%0,%1,%2,%3}, [%4];"
                 : "=r"(r[0]), "=r"(r[1]), "=r"(r[2]), "=r"(r[3]) : "r"(saddr));
}

// Fine-grained streaming tail-copy chunk: x[:,64:,:] -> out[:,64:,:]
// 15 chunks per batch exactly (184320 / 12288), division-free.
#define CCHUNK 12288
__device__ __forceinline__ void copy_chunk(int cb, const float4* __restrict__ src,
                                           float4* __restrict__ dst, int tid) {
    int b    = cb / 15;                  // compile-time-strength-reduced (cb < 960)
    int part = cb - b * 15;
    long long off = (long long)b * (PS * (PF / 4)) + PP2 * (PF / 4)
                  + (long long)part * CCHUNK;
    const float4* s = src + off;
    float4* d = dst + off;
    #pragma unroll 8
    for (int t = tid; t < CCHUNK; t += 256)
        __stcs(d + t, __ldcs(s + t));
}

// ---------------------------------------------------------------------------
// TF32 mma.sync GEMM, ldmatrix fragment loads. Block tile 128x128, BK=32,
// 3-stage cp.async, one __syncthreads per iter. 8 warps 2(M)x4(N), warp 64x32.
// MODE 0: C[4096,2304] = Xw @ [Wq;Wk;Wv]^T + bias -> g_qkv; grid (32,18)
// MODE 1: C[4096, 768] = O @ Wo^T + bo -> d_out (s < 64);   grid (32,6)
// ---------------------------------------------------------------------------
#define BK   32
#define LDK  36                         // 32 + 4: LDSM rows stride 9*16B -> conflict-free
#define STAGEF ((128 + 128) * LDK)      // 9216 floats / stage
#define NSTG 3
#define DSMEM  (NSTG * STAGEF * 4)      // 110592 B -> 2 CTAs/SM
#define NKI  (PF / BK)                  // 24

template <int MODE>
__global__ void __launch_bounds__(256, 2) tc_gemm(
    const float* __restrict__ A,
    const float* __restrict__ W0, const float* __restrict__ W1, const float* __restrict__ W2,
    const float* __restrict__ b0, const float* __restrict__ b1, const float* __restrict__ b2,
    float* __restrict__ Cout)
{
    extern __shared__ float sm[];
    const int tid = threadIdx.x;

    const int bx = blockIdx.x;
    const int ny = blockIdx.y;

    const int wid  = tid >> 5;
    const int lane = tid & 31;
    const int wm   = wid >> 2;           // 0..1
    const int wn   = wid & 3;            // 0..3
    const int g    = lane >> 2;          // 0..7
    const int t4   = lane & 3;           // 0..3
    const int rl   = (lane & 7) | (((lane >> 3) & 1) << 3);  // ldsm row
    const int cl   = ((lane >> 4) & 1) * 4;                  // ldsm col

    const int m0 = bx * 128;
    const float* W; const float* bias; int nbw; int wsel = 0;
    if (MODE == 0) {
        wsel = ny / 6;
        nbw  = (ny % 6) * 128;
        W    = (wsel == 0) ? W0 : (wsel == 1 ? W1 : W2);
        bias = (wsel == 0) ? b0 : (wsel == 1 ? b1 : b2);
    } else {
        W = W0; bias = b0; nbw = ny * 128;
    }
    const float* Ap = (MODE == 0) ? A : g_o;

    // Stage loader: A 128x32 + B 128x32, 4+4 cp16 per thread
    auto load_stage = [&](int buf, int k0) {
        float* As = sm + buf * STAGEF;
        float* Bs = As + 128 * LDK;
        #pragma unroll
        for (int p = 0; p < 4; p++) {
            int idx = tid + p * 256;
            int r = idx >> 3, c4 = (idx & 7) * 4;
            int gm = m0 + r;
            const float* ga = (MODE == 0)
                ? Ap + ((long long)(gm >> 6) * PS + (gm & 63)) * PF + k0 + c4
                : Ap + (long long)gm * PF + k0 + c4;
            cp16(&As[r * LDK + c4], ga);
        }
        #pragma unroll
        for (int p = 0; p < 4; p++) {
            int idx = tid + p * 256;
            int r = idx >> 3, c4 = (idx & 7) * 4;
            const float* gb = W + (long long)(nbw + r) * PF + k0 + c4;
            cp16(&Bs[r * LDK + c4], gb);
        }
    };

    float acc[4][4][4];
    #pragma unroll
    for (int mi = 0; mi < 4; mi++)
        #pragma unroll
        for (int ni = 0; ni < 4; ni++)
            #pragma unroll
            for (int q = 0; q < 4; q++) acc[mi][ni][q] = 0.0f;

    load_stage(0, 0);
    cp_commit();
    load_stage(1, BK);
    cp_commit();

    const unsigned sm_sa = (unsigned)__cvta_generic_to_shared(sm);

    int buf = 0;
    for (int i = 0; i < NKI; i++) {
        if (i < NKI - 1) { cp_wait<1>(); } else { cp_wait<0>(); }
        __syncthreads();
        if (i + 2 < NKI) {
            int lb = buf + 2; if (lb >= NSTG) lb -= NSTG;
            load_stage(lb, (i + 2) * BK);
            cp_commit();
        }

        const unsigned stage_sa = sm_sa + buf * (STAGEF * 4);
        const unsigned a_sa = stage_sa + ((wm * 64 + rl) * LDK + cl) * 4;
        const unsigned b_sa = stage_sa + ((128 + wn * 32 + rl) * LDK + cl) * 4;

        #pragma unroll
        for (int kk = 0; kk < BK; kk += 8) {
            unsigned af[4][4];
            #pragma unroll
            for (int mi = 0; mi < 4; mi++)
                ldsm4(af[mi], a_sa + (mi * 16 * LDK + kk) * 4);
            unsigned bf[4][2];
            #pragma unroll
            for (int np = 0; np < 2; np++) {
                unsigned t[4];
                ldsm4(t, b_sa + (np * 16 * LDK + kk) * 4);
                bf[2 * np][0]     = t[0];
                bf[2 * np + 1][0] = t[1];
                bf[2 * np][1]     = t[2];
                bf[2 * np + 1][1] = t[3];
            }
            #pragma unroll
            for (int mi = 0; mi < 4; mi++)
                #pragma unroll
                for (int ni = 0; ni < 4; ni++)
                    mma_tf32(acc[mi][ni], af[mi], bf[ni]);
        }

        buf++; if (buf >= NSTG) buf -= NSTG;
    }

    // Bias per ni (float2, col pair this thread owns)
    float2 bfrag[4];
    #pragma unroll
    for (int ni = 0; ni < 4; ni++)
        bfrag[ni] = *reinterpret_cast<const float2*>(bias + nbw + wn * 32 + ni * 8 + t4 * 2);

    // Epilogue: direct global float2 stores from accumulators
    #pragma unroll
    for (int mi = 0; mi < 4; mi++) {
        #pragma unroll
        for (int half = 0; half < 2; half++) {
            int gm = m0 + wm * 64 + mi * 16 + g + half * 8;
            int bb_ = gm >> 6, ss_ = gm & 63;
            #pragma unroll
            for (int ni = 0; ni < 4; ni++) {
                int n = nbw + wn * 32 + ni * 8 + t4 * 2;
                float2 v;
                v.x = acc[mi][ni][half * 2 + 0] + bfrag[ni].x;
                v.y = acc[mi][ni][half * 2 + 1] + bfrag[ni].y;
                if (MODE == 0) {
                    int h = n >> 6, d = n & 63;
                    float* dst = g_qkv + (long long)wsel * QKVSTRIDE
                               + (long long)(bb_ * PH + h) * HEADSZ + ss_ * 64 + d;
                    *reinterpret_cast<float2*>(dst) = v;
                } else {
                    float* dst = Cout + ((long long)bb_ * PS + ss_) * PF + n;
                    *reinterpret_cast<float2*>(dst) = v;
                }
            }
        }
    }
}

// ---------------------------------------------------------------------------
// Attention (blocks 0..767) + ALL copy chunks (blocks 768..1727).
// Static smem 48KB -> good CTA occupancy for both block types.
// ---------------------------------------------------------------------------
__global__ void __launch_bounds__(256) attn_copy_kernel(const float4* __restrict__ x,
                                                        float4* __restrict__ out) {
    __shared__ float sq[64 * 64];
    __shared__ float sk[64 * 64];
    __shared__ float ss[64 * 64];

    const int tid = threadIdx.x;

    if (blockIdx.x >= PB * PH) {
        copy_chunk(blockIdx.x - PB * PH, x, out, tid);
        return;
    }

    const int b = blockIdx.x / PH;
    const int h = blockIdx.x % PH;
    const float* qg = g_qkv + (long long)(b * PH + h) * HEADSZ;
    const float* kg = qg + (long long)QKVSTRIDE;
    const float* vg = kg + (long long)QKVSTRIDE;
    const int lane = tid & 31;

    for (int t = tid; t < 1024; t += 256)
        reinterpret_cast<float4*>(sq)[t] = reinterpret_cast<const float4*>(qg)[t];
    for (int t = tid; t < 1024; t += 256) {
        int j = t >> 4, d4 = (t & 15) * 4;
        float4 v = reinterpret_cast<const float4*>(kg)[t];
        *reinterpret_cast<float4*>(&sk[j * 64 + (d4 ^ ((j & 7) << 3))]) = v;
    }
    __syncthreads();

    #pragma unroll
    for (int t = 0; t < 16; t++) {
        int idx = tid + (t << 8);
        int i = idx >> 6, j = idx & 63;
        int sw = (j & 7) << 3;
        float s = 0.f;
        #pragma unroll
        for (int dd = 0; dd < 64; dd += 4) {
            float4 q4 = *reinterpret_cast<const float4*>(&sq[i * 64 + dd]);
            float4 k4 = *reinterpret_cast<const float4*>(&sk[j * 64 + (dd ^ sw)]);
            s += q4.x * k4.x + q4.y * k4.y + q4.z * k4.z + q4.w * k4.w;
        }
        ss[idx] = s * 0.125f;
    }
    __syncthreads();

    {
        int w = tid >> 5;
        #pragma unroll
        for (int rr = 0; rr < 8; rr++) {
            int i = w * 8 + rr;
            float x0 = ss[i * 64 + lane];
            float x1 = ss[i * 64 + 32 + lane];
            float m = fmaxf(x0, x1);
            #pragma unroll
            for (int o = 16; o; o >>= 1) m = fmaxf(m, __shfl_xor_sync(0xffffffffu, m, o));
            float e0 = __expf(x0 - m), e1 = __expf(x1 - m);
            float sum = e0 + e1;
            #pragma unroll
            for (int o = 16; o; o >>= 1) sum += __shfl_xor_sync(0xffffffffu, sum, o);
            float inv = 1.0f / sum;
            ss[i * 64 + lane]      = e0 * inv;
            ss[i * 64 + 32 + lane] = e1 * inv;
        }
    }
    __syncthreads();

    for (int t = tid; t < 1024; t += 256)
        reinterpret_cast<float4*>(sq)[t] = reinterpret_cast<const float4*>(vg)[t];
    __syncthreads();

    #pragma unroll
    for (int t = 0; t < 4; t++) {
        int gidx = tid + (t << 8);
        int i  = gidx >> 4;
        int d4 = (gidx & 15) * 4;
        float ox = 0.f, oy = 0.f, oz = 0.f, ow = 0.f;
        #pragma unroll 16
        for (int j = 0; j < 64; j++) {
            float a = ss[i * 64 + j];
            float4 v4 = *reinterpret_cast<const float4*>(&sq[j * 64 + d4]);
            ox += a * v4.x; oy += a * v4.y; oz += a * v4.z; ow += a * v4.w;
        }
        float4 o4; o4.x = ox; o4.y = oy; o4.z = oz; o4.w = ow;
        *reinterpret_cast<float4*>(&g_o[(long long)(b * 64 + i) * PF + h * 64 + d4]) = o4;
    }
}

// ---------------------------------------------------------------------------
extern "C" void kernel_launch(void* const* d_in, const int* in_sizes, int n_in,
                              void* d_out, int out_size) {
    const float* x  = (const float*)d_in[0];
    const float* Wq = (const float*)d_in[1];
    const float* bq = (const float*)d_in[2];
    const float* Wk = (const float*)d_in[3];
    const float* bk = (const float*)d_in[4];
    const float* Wv = (const float*)d_in[5];
    const float* bv = (const float*)d_in[6];
    const float* Wo = (const float*)d_in[7];
    const float* bo = (const float*)d_in[8];
    float* out = (float*)d_out;

    cudaFuncSetAttribute(tc_gemm<0>, cudaFuncAttributeMaxDynamicSharedMemorySize, DSMEM);
    cudaFuncSetAttribute(tc_gemm<1>, cudaFuncAttributeMaxDynamicSharedMemorySize, DSMEM);

    // 1) QKV projection (+bias) into g_qkv: pure GEMM, grid (32,18)
    tc_gemm<0><<<dim3(32, 18), 256, DSMEM>>>(x, Wq, Wk, Wv, bq, bk, bv, nullptr);

    // 2) attention per (b,h) + ALL 960 tail-copy chunks (low-smem launch)
    attn_copy_kernel<<<PB * PH + 960, 256>>>((const float4*)x, (float4*)out);

    // 3) output projection (+bo) into d_out[:, :64, :]: pure GEMM, grid (32,6)
    tc_gemm<1><<<dim3(32, 6), 256, DSMEM>>>(nullptr, Wo, nullptr, nullptr,
                                            bo, nullptr, nullptr, out);
}

// round 14
// speedup vs baseline: 1.2941x; 1.2941x over previous
#include <cuda_runtime.h>
#include <cstdint>

// Problem constants
#define PB   64
#define PS   1024
#define PF   768
#define PH   12
#define PP2  64
#define HEADSZ 4096
#define QKVSTRIDE (PB * PH * HEADSZ)   // 3,145,728

__device__ float g_qkv[3LL * QKVSTRIDE];
__device__ float g_o[4096LL * PF];

// ---------------------------------------------------------------------------
// PTX helpers
// ---------------------------------------------------------------------------
__device__ __forceinline__ void cp16(void* s, const void* g) {
    unsigned sa = (unsigned)__cvta_generic_to_shared(s);
    asm volatile("cp.async.cg.shared.global [%0], [%1], 16;\n" :: "r"(sa), "l"(g));
}
__device__ __forceinline__ void cp_commit() { asm volatile("cp.async.commit_group;\n"); }
template <int N>
__device__ __forceinline__ void cp_wait() { asm volatile("cp.async.wait_group %0;\n" :: "n"(N)); }

__device__ __forceinline__ void mma_tf32(float* c, const unsigned* a, const unsigned* b) {
    asm volatile(
        "mma.sync.aligned.m16n8k8.row.col.f32.tf32.tf32.f32 "
        "{%0,%1,%2,%3}, {%4,%5,%6,%7}, {%8,%9}, {%0,%1,%2,%3};"
        : "+f"(c[0]), "+f"(c[1]), "+f"(c[2]), "+f"(c[3])
        : "r"(a[0]), "r"(a[1]), "r"(a[2]), "r"(a[3]), "r"(b[0]), "r"(b[1]));
}

// Tail geometry (float4 units): tail has 64 batches x 184320 float4.
#define TPERB 184320                    // (PS-PP2)*(PF/4)
#define TROW  196608                    // PS*(PF/4)
#define TSKIP 12288                     // PP2*(PF/4)

// Fine-grained tail-copy chunk (attn launch): 12288 float4 each.
#define CCHUNK 12288
__device__ __forceinline__ void copy_chunk(int cb, const float4* __restrict__ src,
                                           float4* __restrict__ dst, int tid) {
    int base = cb * CCHUNK;
    #pragma unroll 4
    for (int t = tid; t < CCHUNK; t += 256) {
        int i = base + t;
        int b = i / TPERB;
        int rem = i - b * TPERB;
        long long off = (long long)b * TROW + TSKIP + rem;
        dst[off] = src[off];
    }
}

// ---------------------------------------------------------------------------
// TF32 mma.sync GEMM (R5-proven core). Block tile 128x128, BK=32, 2-stage
// cp.async. 8 warps 2(M)x4(N), warp tile 64x32, scalar-LDS fragments.
// MODE 0: C[4096,2304] = Xw @ [Wq;Wk;Wv]^T + bias -> g_qkv; grid (32,18).
//         ALSO streams 10240 float4/block of the out-tail copy through a
//         16KB smem staging area inside the mainloop (chunks 0..19).
// MODE 1: C[4096, 768] = O @ Wo^T + bo -> d_out (s < 64); grid (32,6).
// ---------------------------------------------------------------------------
#define BK   32
#define LDK  36                         // 32 + 4: 16B-aligned rows, conflict-free frags
#define STAGEF ((128 + 128) * LDK)      // 9216 floats / stage
#define CPSTAGE 2048                    // 512 float4 = 2048 floats per copy stage
#define DSMEM  ((2 * STAGEF + 2 * CPSTAGE) * 4)   // 90112 B -> 2 CTAs/SM
#define NKI  (PF / BK)                  // 24
#define NCPCHUNK 20                     // 20 chunks x 512 float4 = 10240 per block

template <int MODE>
__global__ void __launch_bounds__(256, 2) tc_gemm(
    const float* __restrict__ A,
    const float* __restrict__ W0, const float* __restrict__ W1, const float* __restrict__ W2,
    const float* __restrict__ b0, const float* __restrict__ b1, const float* __restrict__ b2,
    float* __restrict__ Cout)
{
    extern __shared__ float sm[];

    const int tid  = threadIdx.x;
    const int wid  = tid >> 5;
    const int lane = tid & 31;
    const int wm   = wid >> 2;           // 0..1
    const int wn   = wid & 3;            // 0..3
    const int g    = lane >> 2;          // 0..7
    const int t4   = lane & 3;           // 0..3

    const int m0 = blockIdx.x * 128;
    const int ny = blockIdx.y;
    const float* W; const float* bias; int nbw; int wsel = 0;
    if (MODE == 0) {
        wsel = ny / 6;
        nbw  = (ny % 6) * 128;
        W    = (wsel == 0) ? W0 : (wsel == 1 ? W1 : W2);
        bias = (wsel == 0) ? b0 : (wsel == 1 ? b1 : b2);
    } else {
        W = W0; bias = b0; nbw = ny * 128;
    }
    const float* Ap = (MODE == 0) ? A : g_o;

    // This block's share of the tail copy (MODE 0 only): 10240 float4.
    const int cpbase = (MODE == 0) ? (ny * 32 + blockIdx.x) * (NCPCHUNK * 512) : 0;

    // Stage loader: A 128x32 + B 128x32 (4+4 cp16/thread), plus one 512-float4
    // copy chunk (2 cp16/thread) into the staging double-buffer.
    auto load_stage = [&](int buf, int k0, int ci) {
        float* As = sm + buf * STAGEF;
        float* Bs = As + 128 * LDK;
        #pragma unroll
        for (int p = 0; p < 4; p++) {
            int idx = tid + p * 256;
            int r = idx >> 3, c4 = (idx & 7) * 4;
            int gm = m0 + r;
            const float* ga = (MODE == 0)
                ? Ap + ((long long)(gm >> 6) * PS + (gm & 63)) * PF + k0 + c4
                : Ap + (long long)gm * PF + k0 + c4;
            cp16(&As[r * LDK + c4], ga);
        }
        #pragma unroll
        for (int p = 0; p < 4; p++) {
            int idx = tid + p * 256;
            int r = idx >> 3, c4 = (idx & 7) * 4;
            const float* gb = W + (long long)(nbw + r) * PF + k0 + c4;
            cp16(&Bs[r * LDK + c4], gb);
        }
        if (MODE == 0 && ci < NCPCHUNK) {
            float* cbuf = sm + 2 * STAGEF + (ci & 1) * CPSTAGE;
            #pragma unroll
            for (int q = 0; q < 2; q++) {
                int idx = cpbase + ci * 512 + q * 256 + tid;
                int b = idx / TPERB;
                int rem = idx - b * TPERB;
                const float4* gsrc = (const float4*)A + ((long long)b * TROW + TSKIP + rem);
                cp16(&cbuf[(q * 256 + tid) * 4], gsrc);
            }
        }
    };

    float acc[4][4][4];
    #pragma unroll
    for (int mi = 0; mi < 4; mi++)
        #pragma unroll
        for (int ni = 0; ni < 4; ni++)
            #pragma unroll
            for (int q = 0; q < 4; q++) acc[mi][ni][q] = 0.0f;

    load_stage(0, 0, 0);
    cp_commit();

    for (int i = 0; i < NKI; i++) {
        if (i + 1 < NKI) {
            load_stage((i + 1) & 1, (i + 1) * BK, i + 1);
            cp_commit();
            cp_wait<1>();
        } else {
            cp_wait<0>();
        }
        __syncthreads();

        const float* As = sm + (i & 1) * STAGEF;
        const float* Bs = As + 128 * LDK;
        const float* ab = As + (wm * 64 + g) * LDK + t4;
        const float* bb = Bs + (wn * 32 + g) * LDK + t4;

        #pragma unroll
        for (int kk = 0; kk < BK; kk += 8) {
            unsigned af[4][4];
            #pragma unroll
            for (int mi = 0; mi < 4; mi++) {
                const float* p = ab + mi * 16 * LDK + kk;
                af[mi][0] = __float_as_uint(p[0]);
                af[mi][1] = __float_as_uint(p[8 * LDK]);
                af[mi][2] = __float_as_uint(p[4]);
                af[mi][3] = __float_as_uint(p[8 * LDK + 4]);
            }
            unsigned bf[4][2];
            #pragma unroll
            for (int ni = 0; ni < 4; ni++) {
                const float* p = bb + ni * 8 * LDK + kk;
                bf[ni][0] = __float_as_uint(p[0]);
                bf[ni][1] = __float_as_uint(p[4]);
            }
            #pragma unroll
            for (int mi = 0; mi < 4; mi++)
                #pragma unroll
                for (int ni = 0; ni < 4; ni++)
                    mma_tf32(acc[mi][ni], af[mi], bf[ni]);
        }

        // Drain copy chunk i (cp.async'd last iter, completed by the wait):
        // LDS -> streaming STG. Transient registers only.
        if (MODE == 0 && i < NCPCHUNK) {
            const float* cbuf = sm + 2 * STAGEF + (i & 1) * CPSTAGE;
            #pragma unroll
            for (int q = 0; q < 2; q++) {
                int idx = cpbase + i * 512 + q * 256 + tid;
                int b = idx / TPERB;
                int rem = idx - b * TPERB;
                float4 v = *reinterpret_cast<const float4*>(&cbuf[(q * 256 + tid) * 4]);
                __stcs((float4*)Cout + ((long long)b * TROW + TSKIP + rem), v);
            }
        }
        __syncthreads();
    }

    // Bias per ni (float2, col pair this thread owns)
    float2 bfrag[4];
    #pragma unroll
    for (int ni = 0; ni < 4; ni++)
        bfrag[ni] = *reinterpret_cast<const float2*>(bias + nbw + wn * 32 + ni * 8 + t4 * 2);

    // Epilogue: direct global float2 stores from accumulators
    #pragma unroll
    for (int mi = 0; mi < 4; mi++) {
        #pragma unroll
        for (int half = 0; half < 2; half++) {
            int gm = m0 + wm * 64 + mi * 16 + g + half * 8;
            int bb_ = gm >> 6, ss_ = gm & 63;
            #pragma unroll
            for (int ni = 0; ni < 4; ni++) {
                int n = nbw + wn * 32 + ni * 8 + t4 * 2;
                float2 v;
                v.x = acc[mi][ni][half * 2 + 0] + bfrag[ni].x;
                v.y = acc[mi][ni][half * 2 + 1] + bfrag[ni].y;
                if (MODE == 0) {
                    int h = n >> 6, d = n & 63;
                    float* dst = g_qkv + (long long)wsel * QKVSTRIDE
                               + (long long)(bb_ * PH + h) * HEADSZ + ss_ * 64 + d;
                    *reinterpret_cast<float2*>(dst) = v;
                } else {
                    float* dst = Cout + ((long long)bb_ * PS + ss_) * PF + n;
                    *reinterpret_cast<float2*>(dst) = v;
                }
            }
        }
    }
}

// ---------------------------------------------------------------------------
// Attention (blocks 0..767) + remaining copy chunks 480..959 (blocks 768..1247)
// ---------------------------------------------------------------------------
__global__ void __launch_bounds__(256) attn_copy_kernel(const float4* __restrict__ x,
                                                        float4* __restrict__ out) {
    __shared__ float sq[64 * 64];
    __shared__ float sk[64 * 64];
    __shared__ float ss[64 * 64];

    const int tid = threadIdx.x;

    if (blockIdx.x >= PB * PH) {
        copy_chunk(blockIdx.x - PB * PH + 480, x, out, tid);
        return;
    }

    const int b = blockIdx.x / PH;
    const int h = blockIdx.x % PH;
    const float* qg = g_qkv + (long long)(b * PH + h) * HEADSZ;
    const float* kg = qg + (long long)QKVSTRIDE;
    const float* vg = kg + (long long)QKVSTRIDE;
    const int lane = tid & 31;

    for (int t = tid; t < 1024; t += 256)
        reinterpret_cast<float4*>(sq)[t] = reinterpret_cast<const float4*>(qg)[t];
    for (int t = tid; t < 1024; t += 256) {
        int j = t >> 4, d4 = (t & 15) * 4;
        float4 v = reinterpret_cast<const float4*>(kg)[t];
        *reinterpret_cast<float4*>(&sk[j * 64 + (d4 ^ ((j & 7) << 3))]) = v;
    }
    __syncthreads();

    #pragma unroll
    for (int t = 0; t < 16; t++) {
        int idx = tid + (t << 8);
        int i = idx >> 6, j = idx & 63;
        int sw = (j & 7) << 3;
        float s = 0.f;
        #pragma unroll
        for (int dd = 0; dd < 64; dd += 4) {
            float4 q4 = *reinterpret_cast<const float4*>(&sq[i * 64 + dd]);
            float4 k4 = *reinterpret_cast<const float4*>(&sk[j * 64 + (dd ^ sw)]);
            s += q4.x * k4.x + q4.y * k4.y + q4.z * k4.z + q4.w * k4.w;
        }
        ss[idx] = s * 0.125f;
    }
    __syncthreads();

    {
        int w = tid >> 5;
        #pragma unroll
        for (int rr = 0; rr < 8; rr++) {
            int i = w * 8 + rr;
            float x0 = ss[i * 64 + lane];
            float x1 = ss[i * 64 + 32 + lane];
            float m = fmaxf(x0, x1);
            #pragma unroll
            for (int o = 16; o; o >>= 1) m = fmaxf(m, __shfl_xor_sync(0xffffffffu, m, o));
            float e0 = __expf(x0 - m), e1 = __expf(x1 - m);
            float sum = e0 + e1;
            #pragma unroll
            for (int o = 16; o; o >>= 1) sum += __shfl_xor_sync(0xffffffffu, sum, o);
            float inv = 1.0f / sum;
            ss[i * 64 + lane]      = e0 * inv;
            ss[i * 64 + 32 + lane] = e1 * inv;
        }
    }
    __syncthreads();

    for (int t = tid; t < 1024; t += 256)
        reinterpret_cast<float4*>(sq)[t] = reinterpret_cast<const float4*>(vg)[t];
    __syncthreads();

    #pragma unroll
    for (int t = 0; t < 4; t++) {
        int gidx = tid + (t << 8);
        int i  = gidx >> 4;
        int d4 = (gidx & 15) * 4;
        float ox = 0.f, oy = 0.f, oz = 0.f, ow = 0.f;
        #pragma unroll 16
        for (int j = 0; j < 64; j++) {
            float a = ss[i * 64 + j];
            float4 v4 = *reinterpret_cast<const float4*>(&sq[j * 64 + d4]);
            ox += a * v4.x; oy += a * v4.y; oz += a * v4.z; ow += a * v4.w;
        }
        float4 o4; o4.x = ox; o4.y = oy; o4.z = oz; o4.w = ow;
        *reinterpret_cast<float4*>(&g_o[(long long)(b * 64 + i) * PF + h * 64 + d4]) = o4;
    }
}

// ---------------------------------------------------------------------------
extern "C" void kernel_launch(void* const* d_in, const int* in_sizes, int n_in,
                              void* d_out, int out_size) {
    const float* x  = (const float*)d_in[0];
    const float* Wq = (const float*)d_in[1];
    const float* bq = (const float*)d_in[2];
    const float* Wk = (const float*)d_in[3];
    const float* bk = (const float*)d_in[4];
    const float* Wv = (const float*)d_in[5];
    const float* bv = (const float*)d_in[6];
    const float* Wo = (const float*)d_in[7];
    const float* bo = (const float*)d_in[8];
    float* out = (float*)d_out;

    cudaFuncSetAttribute(tc_gemm<0>, cudaFuncAttributeMaxDynamicSharedMemorySize, DSMEM);
    cudaFuncSetAttribute(tc_gemm<1>, cudaFuncAttributeMaxDynamicSharedMemorySize, DSMEM);

    // 1) QKV projection (+bias) into g_qkv, with half the tail copy streamed
    //    through the mainloop (Cout = out carries the copy destination)
    tc_gemm<0><<<dim3(32, 18), 256, DSMEM>>>(x, Wq, Wk, Wv, bq, bk, bv, out);

    // 2) attention per (b,h) + remaining 480 tail-copy chunks
    attn_copy_kernel<<<PB * PH + 480, 256>>>((const float4*)x, (float4*)out);

    // 3) output projection (+bo) into d_out[:, :64, :]
    tc_gemm<1><<<dim3(32, 6), 256, DSMEM>>>(nullptr, Wo, nullptr, nullptr,
                                            bo, nullptr, nullptr, out);
}

// round 15
// speedup vs baseline: 1.3605x; 1.0512x over previous
#include <cuda_runtime.h>
#include <cstdint>

// Problem constants
#define PB   64
#define PS   1024
#define PF   768
#define PH   12
#define PP2  64
#define HEADSZ 4096
#define QKVSTRIDE (PB * PH * HEADSZ)   // 3,145,728

__device__ float g_qkv[3LL * QKVSTRIDE];
__device__ float g_o[4096LL * PF];

// ---------------------------------------------------------------------------
// PTX helpers
// ---------------------------------------------------------------------------
__device__ __forceinline__ void cp16(void* s, const void* g) {
    unsigned sa = (unsigned)__cvta_generic_to_shared(s);
    asm volatile("cp.async.cg.shared.global [%0], [%1], 16;\n" :: "r"(sa), "l"(g));
}
__device__ __forceinline__ void cp_commit() { asm volatile("cp.async.commit_group;\n"); }
template <int N>
__device__ __forceinline__ void cp_wait() { asm volatile("cp.async.wait_group %0;\n" :: "n"(N)); }

__device__ __forceinline__ void mma_tf32(float* c, const unsigned* a, const unsigned* b) {
    asm volatile(
        "mma.sync.aligned.m16n8k8.row.col.f32.tf32.tf32.f32 "
        "{%0,%1,%2,%3}, {%4,%5,%6,%7}, {%8,%9}, {%0,%1,%2,%3};"
        : "+f"(c[0]), "+f"(c[1]), "+f"(c[2]), "+f"(c[3])
        : "r"(a[0]), "r"(a[1]), "r"(a[2]), "r"(a[3]), "r"(b[0]), "r"(b[1]));
}

// Tail geometry (float4 units): tail has 64 batches x 184320 float4.
#define TPERB 184320                    // (PS-PP2)*(PF/4)
#define TROW  196608                    // PS*(PF/4)
#define TSKIP 12288                     // PP2*(PF/4)

// ---------------------------------------------------------------------------
// TF32 mma.sync GEMM (R5-proven core). Block tile 128x128, BK=32, 2-stage
// cp.async. 8 warps 2(M)x4(N), warp tile 64x32, scalar-LDS fragments.
// MODE 0: C[4096,2304] = Xw @ [Wq;Wk;Wv]^T + bias -> g_qkv; grid (32,18).
//         ALSO streams the ENTIRE out-tail copy (20480 float4/block) through
//         a 32KB smem staging double-buffer inside the mainloop.
// MODE 1: C[4096, 768] = O @ Wo^T + bo -> d_out (s < 64); grid (32,6).
// ---------------------------------------------------------------------------
#define BK   32
#define LDK  36                         // 32 + 4: 16B-aligned rows, conflict-free frags
#define STAGEF ((128 + 128) * LDK)      // 9216 floats / stage
#define CPSTAGE 4096                    // 1024 float4 = 4096 floats per copy stage
#define DSMEM  ((2 * STAGEF + 2 * CPSTAGE) * 4)   // 106496 B -> 2 CTAs/SM
#define NKI  (PF / BK)                  // 24
#define NCPCHUNK 20                     // 20 chunks x 1024 float4 = 20480 per block
                                        // 576 blocks x 20480 = 11,796,480 = full tail

template <int MODE>
__global__ void __launch_bounds__(256, 2) tc_gemm(
    const float* __restrict__ A,
    const float* __restrict__ W0, const float* __restrict__ W1, const float* __restrict__ W2,
    const float* __restrict__ b0, const float* __restrict__ b1, const float* __restrict__ b2,
    float* __restrict__ Cout)
{
    extern __shared__ float sm[];

    const int tid  = threadIdx.x;
    const int wid  = tid >> 5;
    const int lane = tid & 31;
    const int wm   = wid >> 2;           // 0..1
    const int wn   = wid & 3;            // 0..3
    const int g    = lane >> 2;          // 0..7
    const int t4   = lane & 3;           // 0..3

    const int m0 = blockIdx.x * 128;
    const int ny = blockIdx.y;
    const float* W; const float* bias; int nbw; int wsel = 0;
    if (MODE == 0) {
        wsel = ny / 6;
        nbw  = (ny % 6) * 128;
        W    = (wsel == 0) ? W0 : (wsel == 1 ? W1 : W2);
        bias = (wsel == 0) ? b0 : (wsel == 1 ? b1 : b2);
    } else {
        W = W0; bias = b0; nbw = ny * 128;
    }
    const float* Ap = (MODE == 0) ? A : g_o;

    // This block's share of the tail copy (MODE 0 only): 20480 float4.
    const int cpbase = (MODE == 0) ? (ny * 32 + blockIdx.x) * (NCPCHUNK * 1024) : 0;

    // Stage loader: A 128x32 + B 128x32 (4+4 cp16/thread), plus one 1024-float4
    // copy chunk (4 cp16/thread) into the staging double-buffer.
    auto load_stage = [&](int buf, int k0, int ci) {
        float* As = sm + buf * STAGEF;
        float* Bs = As + 128 * LDK;
        #pragma unroll
        for (int p = 0; p < 4; p++) {
            int idx = tid + p * 256;
            int r = idx >> 3, c4 = (idx & 7) * 4;
            int gm = m0 + r;
            const float* ga = (MODE == 0)
                ? Ap + ((long long)(gm >> 6) * PS + (gm & 63)) * PF + k0 + c4
                : Ap + (long long)gm * PF + k0 + c4;
            cp16(&As[r * LDK + c4], ga);
        }
        #pragma unroll
        for (int p = 0; p < 4; p++) {
            int idx = tid + p * 256;
            int r = idx >> 3, c4 = (idx & 7) * 4;
            const float* gb = W + (long long)(nbw + r) * PF + k0 + c4;
            cp16(&Bs[r * LDK + c4], gb);
        }
        if (MODE == 0 && ci < NCPCHUNK) {
            float* cbuf = sm + 2 * STAGEF + (ci & 1) * CPSTAGE;
            #pragma unroll
            for (int q = 0; q < 4; q++) {
                int idx = cpbase + ci * 1024 + q * 256 + tid;
                int b = idx / TPERB;
                int rem = idx - b * TPERB;
                const float4* gsrc = (const float4*)A + ((long long)b * TROW + TSKIP + rem);
                cp16(&cbuf[(q * 256 + tid) * 4], gsrc);
            }
        }
    };

    float acc[4][4][4];
    #pragma unroll
    for (int mi = 0; mi < 4; mi++)
        #pragma unroll
        for (int ni = 0; ni < 4; ni++)
            #pragma unroll
            for (int q = 0; q < 4; q++) acc[mi][ni][q] = 0.0f;

    load_stage(0, 0, 0);
    cp_commit();

    for (int i = 0; i < NKI; i++) {
        if (i + 1 < NKI) {
            load_stage((i + 1) & 1, (i + 1) * BK, i + 1);
            cp_commit();
            cp_wait<1>();
        } else {
            cp_wait<0>();
        }
        __syncthreads();

        const float* As = sm + (i & 1) * STAGEF;
        const float* Bs = As + 128 * LDK;
        const float* ab = As + (wm * 64 + g) * LDK + t4;
        const float* bb = Bs + (wn * 32 + g) * LDK + t4;

        #pragma unroll
        for (int kk = 0; kk < BK; kk += 8) {
            unsigned af[4][4];
            #pragma unroll
            for (int mi = 0; mi < 4; mi++) {
                const float* p = ab + mi * 16 * LDK + kk;
                af[mi][0] = __float_as_uint(p[0]);
                af[mi][1] = __float_as_uint(p[8 * LDK]);
                af[mi][2] = __float_as_uint(p[4]);
                af[mi][3] = __float_as_uint(p[8 * LDK + 4]);
            }
            unsigned bf[4][2];
            #pragma unroll
            for (int ni = 0; ni < 4; ni++) {
                const float* p = bb + ni * 8 * LDK + kk;
                bf[ni][0] = __float_as_uint(p[0]);
                bf[ni][1] = __float_as_uint(p[4]);
            }
            #pragma unroll
            for (int mi = 0; mi < 4; mi++)
                #pragma unroll
                for (int ni = 0; ni < 4; ni++)
                    mma_tf32(acc[mi][ni], af[mi], bf[ni]);
        }

        // Drain copy chunk i (cp.async'd last iter, completed by the wait):
        // LDS -> streaming STG. Transient registers only.
        if (MODE == 0 && i < NCPCHUNK) {
            const float* cbuf = sm + 2 * STAGEF + (i & 1) * CPSTAGE;
            #pragma unroll
            for (int q = 0; q < 4; q++) {
                int idx = cpbase + i * 1024 + q * 256 + tid;
                int b = idx / TPERB;
                int rem = idx - b * TPERB;
                float4 v = *reinterpret_cast<const float4*>(&cbuf[(q * 256 + tid) * 4]);
                __stcs((float4*)Cout + ((long long)b * TROW + TSKIP + rem), v);
            }
        }
        __syncthreads();
    }

    // Bias per ni (float2, col pair this thread owns)
    float2 bfrag[4];
    #pragma unroll
    for (int ni = 0; ni < 4; ni++)
        bfrag[ni] = *reinterpret_cast<const float2*>(bias + nbw + wn * 32 + ni * 8 + t4 * 2);

    // Epilogue: direct global float2 stores from accumulators
    #pragma unroll
    for (int mi = 0; mi < 4; mi++) {
        #pragma unroll
        for (int half = 0; half < 2; half++) {
            int gm = m0 + wm * 64 + mi * 16 + g + half * 8;
            int bb_ = gm >> 6, ss_ = gm & 63;
            #pragma unroll
            for (int ni = 0; ni < 4; ni++) {
                int n = nbw + wn * 32 + ni * 8 + t4 * 2;
                float2 v;
                v.x = acc[mi][ni][half * 2 + 0] + bfrag[ni].x;
                v.y = acc[mi][ni][half * 2 + 1] + bfrag[ni].y;
                if (MODE == 0) {
                    int h = n >> 6, d = n & 63;
                    float* dst = g_qkv + (long long)wsel * QKVSTRIDE
                               + (long long)(bb_ * PH + h) * HEADSZ + ss_ * 64 + d;
                    *reinterpret_cast<float2*>(dst) = v;
                } else {
                    float* dst = Cout + ((long long)bb_ * PS + ss_) * PF + n;
                    *reinterpret_cast<float2*>(dst) = v;
                }
            }
        }
    }
}

// ---------------------------------------------------------------------------
// Attention, one block per (b,h). Pure (no copy blocks).
// ---------------------------------------------------------------------------
__global__ void __launch_bounds__(256) attn_kernel() {
    __shared__ float sq[64 * 64];
    __shared__ float sk[64 * 64];
    __shared__ float ss[64 * 64];

    const int tid = threadIdx.x;
    const int b = blockIdx.x / PH;
    const int h = blockIdx.x % PH;
    const float* qg = g_qkv + (long long)(b * PH + h) * HEADSZ;
    const float* kg = qg + (long long)QKVSTRIDE;
    const float* vg = kg + (long long)QKVSTRIDE;
    const int lane = tid & 31;

    for (int t = tid; t < 1024; t += 256)
        reinterpret_cast<float4*>(sq)[t] = reinterpret_cast<const float4*>(qg)[t];
    for (int t = tid; t < 1024; t += 256) {
        int j = t >> 4, d4 = (t & 15) * 4;
        float4 v = reinterpret_cast<const float4*>(kg)[t];
        *reinterpret_cast<float4*>(&sk[j * 64 + (d4 ^ ((j & 7) << 3))]) = v;
    }
    __syncthreads();

    #pragma unroll
    for (int t = 0; t < 16; t++) {
        int idx = tid + (t << 8);
        int i = idx >> 6, j = idx & 63;
        int sw = (j & 7) << 3;
        float s = 0.f;
        #pragma unroll
        for (int dd = 0; dd < 64; dd += 4) {
            float4 q4 = *reinterpret_cast<const float4*>(&sq[i * 64 + dd]);
            float4 k4 = *reinterpret_cast<const float4*>(&sk[j * 64 + (dd ^ sw)]);
            s += q4.x * k4.x + q4.y * k4.y + q4.z * k4.z + q4.w * k4.w;
        }
        ss[idx] = s * 0.125f;
    }
    __syncthreads();

    {
        int w = tid >> 5;
        #pragma unroll
        for (int rr = 0; rr < 8; rr++) {
            int i = w * 8 + rr;
            float x0 = ss[i * 64 + lane];
            float x1 = ss[i * 64 + 32 + lane];
            float m = fmaxf(x0, x1);
            #pragma unroll
            for (int o = 16; o; o >>= 1) m = fmaxf(m, __shfl_xor_sync(0xffffffffu, m, o));
            float e0 = __expf(x0 - m), e1 = __expf(x1 - m);
            float sum = e0 + e1;
            #pragma unroll
            for (int o = 16; o; o >>= 1) sum += __shfl_xor_sync(0xffffffffu, sum, o);
            float inv = 1.0f / sum;
            ss[i * 64 + lane]      = e0 * inv;
            ss[i * 64 + 32 + lane] = e1 * inv;
        }
    }
    __syncthreads();

    for (int t = tid; t < 1024; t += 256)
        reinterpret_cast<float4*>(sq)[t] = reinterpret_cast<const float4*>(vg)[t];
    __syncthreads();

    #pragma unroll
    for (int t = 0; t < 4; t++) {
        int gidx = tid + (t << 8);
        int i  = gidx >> 4;
        int d4 = (gidx & 15) * 4;
        float ox = 0.f, oy = 0.f, oz = 0.f, ow = 0.f;
        #pragma unroll 16
        for (int j = 0; j < 64; j++) {
            float a = ss[i * 64 + j];
            float4 v4 = *reinterpret_cast<const float4*>(&sq[j * 64 + d4]);
            ox += a * v4.x; oy += a * v4.y; oz += a * v4.z; ow += a * v4.w;
        }
        float4 o4; o4.x = ox; o4.y = oy; o4.z = oz; o4.w = ow;
        *reinterpret_cast<float4*>(&g_o[(long long)(b * 64 + i) * PF + h * 64 + d4]) = o4;
    }
}

// ---------------------------------------------------------------------------
extern "C" void kernel_launch(void* const* d_in, const int* in_sizes, int n_in,
                              void* d_out, int out_size) {
    const float* x  = (const float*)d_in[0];
    const float* Wq = (const float*)d_in[1];
    const float* bq = (const float*)d_in[2];
    const float* Wk = (const float*)d_in[3];
    const float* bk = (const float*)d_in[4];
    const float* Wv = (const float*)d_in[5];
    const float* bv = (const float*)d_in[6];
    const float* Wo = (const float*)d_in[7];
    const float* bo = (const float*)d_in[8];
    float* out = (float*)d_out;

    cudaFuncSetAttribute(tc_gemm<0>, cudaFuncAttributeMaxDynamicSharedMemorySize, DSMEM);
    cudaFuncSetAttribute(tc_gemm<1>, cudaFuncAttributeMaxDynamicSharedMemorySize, DSMEM);

    // 1) QKV projection (+bias) into g_qkv + ENTIRE tail copy streamed
    //    through the mainloop (Cout = out carries the copy destination)
    tc_gemm<0><<<dim3(32, 18), 256, DSMEM>>>(x, Wq, Wk, Wv, bq, bk, bv, out);

    // 2) attention per (b,h), pure
    attn_kernel<<<PB * PH, 256>>>();

    // 3) output projection (+bo) into d_out[:, :64, :]
    tc_gemm<1><<<dim3(32, 6), 256, DSMEM>>>(nullptr, Wo, nullptr, nullptr,
                                            bo, nullptr, nullptr, out);
}

// round 16
// speedup vs baseline: 1.4015x; 1.0302x over previous
#include <cuda_runtime.h>
#include <cstdint>

// Problem constants
#define PB   64
#define PS   1024
#define PF   768
#define PH   12
#define PP2  64
#define HEADSZ 4096
#define QKVSTRIDE (PB * PH * HEADSZ)   // 3,145,728

__device__ float g_qkv[3LL * QKVSTRIDE];
__device__ float g_o[4096LL * PF];
__device__ int   g_sync[608];          // [0,576): gemm0 tile flags; [576,608): per-batch-pair attn counters

// ---------------------------------------------------------------------------
// PTX helpers
// ---------------------------------------------------------------------------
__device__ __forceinline__ void cp16(void* s, const void* g) {
    unsigned sa = (unsigned)__cvta_generic_to_shared(s);
    asm volatile("cp.async.cg.shared.global [%0], [%1], 16;\n" :: "r"(sa), "l"(g));
}
__device__ __forceinline__ void cp_commit() { asm volatile("cp.async.commit_group;\n"); }
template <int N>
__device__ __forceinline__ void cp_wait() { asm volatile("cp.async.wait_group %0;\n" :: "n"(N)); }

__device__ __forceinline__ void mma_tf32(float* c, const unsigned* a, const unsigned* b) {
    asm volatile(
        "mma.sync.aligned.m16n8k8.row.col.f32.tf32.tf32.f32 "
        "{%0,%1,%2,%3}, {%4,%5,%6,%7}, {%8,%9}, {%0,%1,%2,%3};"
        : "+f"(c[0]), "+f"(c[1]), "+f"(c[2]), "+f"(c[3])
        : "r"(a[0]), "r"(a[1]), "r"(a[2]), "r"(a[3]), "r"(b[0]), "r"(b[1]));
}

__device__ __forceinline__ void wait_flag(const int* p, int target) {
    while (*(volatile const int*)p < target) __nanosleep(200);
}

// Tail geometry (float4 units)
#define TPERB 184320                    // (PS-PP2)*(PF/4)
#define TROW  196608                    // PS*(PF/4)
#define TSKIP 12288                     // PP2*(PF/4)

// GEMM config (R15-proven core)
#define BK   32
#define LDK  36
#define STAGEF ((128 + 128) * LDK)      // 9216 floats / stage
#define CPSTAGE 4096                    // 1024 float4 per copy stage
#define DSMEM  ((2 * STAGEF + 2 * CPSTAGE) * 4)   // 106496 B -> 2 CTAs/SM
#define NKI  (PF / BK)                  // 24
#define NCPCHUNK 20                     // 20 x 1024 float4 x 576 blocks = full tail

// ---------------------------------------------------------------------------
// GEMM body. MODE 0: QKV projection (+full tail copy). MODE 1: out projection.
// ---------------------------------------------------------------------------
template <int MODE>
__device__ __forceinline__ void gemm_body(
    int bx, int ny, float* sm,
    const float* __restrict__ A,
    const float* __restrict__ W0, const float* __restrict__ W1, const float* __restrict__ W2,
    const float* __restrict__ b0, const float* __restrict__ b1, const float* __restrict__ b2,
    float* __restrict__ Cout)
{
    const int tid  = threadIdx.x;
    const int wid  = tid >> 5;
    const int lane = tid & 31;
    const int wm   = wid >> 2;
    const int wn   = wid & 3;
    const int g    = lane >> 2;
    const int t4   = lane & 3;

    const int m0 = bx * 128;
    const float* W; const float* bias; int nbw; int wsel = 0;
    if (MODE == 0) {
        wsel = ny / 6;
        nbw  = (ny % 6) * 128;
        W    = (wsel == 0) ? W0 : (wsel == 1 ? W1 : W2);
        bias = (wsel == 0) ? b0 : (wsel == 1 ? b1 : b2);
    } else {
        W = W0; bias = b0; nbw = ny * 128;
    }
    const float* Ap = (MODE == 0) ? A : g_o;

    const int cpbase = (MODE == 0) ? (ny * 32 + bx) * (NCPCHUNK * 1024) : 0;

    auto load_stage = [&](int buf, int k0, int ci) {
        float* As = sm + buf * STAGEF;
        float* Bs = As + 128 * LDK;
        #pragma unroll
        for (int p = 0; p < 4; p++) {
            int idx = tid + p * 256;
            int r = idx >> 3, c4 = (idx & 7) * 4;
            int gm = m0 + r;
            const float* ga = (MODE == 0)
                ? Ap + ((long long)(gm >> 6) * PS + (gm & 63)) * PF + k0 + c4
                : Ap + (long long)gm * PF + k0 + c4;
            cp16(&As[r * LDK + c4], ga);
        }
        #pragma unroll
        for (int p = 0; p < 4; p++) {
            int idx = tid + p * 256;
            int r = idx >> 3, c4 = (idx & 7) * 4;
            const float* gb = W + (long long)(nbw + r) * PF + k0 + c4;
            cp16(&Bs[r * LDK + c4], gb);
        }
        if (MODE == 0 && ci < NCPCHUNK) {
            float* cbuf = sm + 2 * STAGEF + (ci & 1) * CPSTAGE;
            #pragma unroll
            for (int q = 0; q < 4; q++) {
                int idx = cpbase + ci * 1024 + q * 256 + tid;
                int b = idx / TPERB;
                int rem = idx - b * TPERB;
                const float4* gsrc = (const float4*)A + ((long long)b * TROW + TSKIP + rem);
                cp16(&cbuf[(q * 256 + tid) * 4], gsrc);
            }
        }
    };

    float acc[4][4][4];
    #pragma unroll
    for (int mi = 0; mi < 4; mi++)
        #pragma unroll
        for (int ni = 0; ni < 4; ni++)
            #pragma unroll
            for (int q = 0; q < 4; q++) acc[mi][ni][q] = 0.0f;

    load_stage(0, 0, 0);
    cp_commit();

    for (int i = 0; i < NKI; i++) {
        if (i + 1 < NKI) {
            load_stage((i + 1) & 1, (i + 1) * BK, i + 1);
            cp_commit();
            cp_wait<1>();
        } else {
            cp_wait<0>();
        }
        __syncthreads();

        const float* As = sm + (i & 1) * STAGEF;
        const float* Bs = As + 128 * LDK;
        const float* ab = As + (wm * 64 + g) * LDK + t4;
        const float* bb = Bs + (wn * 32 + g) * LDK + t4;

        #pragma unroll
        for (int kk = 0; kk < BK; kk += 8) {
            unsigned af[4][4];
            #pragma unroll
            for (int mi = 0; mi < 4; mi++) {
                const float* p = ab + mi * 16 * LDK + kk;
                af[mi][0] = __float_as_uint(p[0]);
                af[mi][1] = __float_as_uint(p[8 * LDK]);
                af[mi][2] = __float_as_uint(p[4]);
                af[mi][3] = __float_as_uint(p[8 * LDK + 4]);
            }
            unsigned bf[4][2];
            #pragma unroll
            for (int ni = 0; ni < 4; ni++) {
                const float* p = bb + ni * 8 * LDK + kk;
                bf[ni][0] = __float_as_uint(p[0]);
                bf[ni][1] = __float_as_uint(p[4]);
            }
            #pragma unroll
            for (int mi = 0; mi < 4; mi++)
                #pragma unroll
                for (int ni = 0; ni < 4; ni++)
                    mma_tf32(acc[mi][ni], af[mi], bf[ni]);
        }

        if (MODE == 0 && i < NCPCHUNK) {
            const float* cbuf = sm + 2 * STAGEF + (i & 1) * CPSTAGE;
            #pragma unroll
            for (int q = 0; q < 4; q++) {
                int idx = cpbase + i * 1024 + q * 256 + tid;
                int b = idx / TPERB;
                int rem = idx - b * TPERB;
                float4 v = *reinterpret_cast<const float4*>(&cbuf[(q * 256 + tid) * 4]);
                __stcs((float4*)Cout + ((long long)b * TROW + TSKIP + rem), v);
            }
        }
        __syncthreads();
    }

    float2 bfrag[4];
    #pragma unroll
    for (int ni = 0; ni < 4; ni++)
        bfrag[ni] = *reinterpret_cast<const float2*>(bias + nbw + wn * 32 + ni * 8 + t4 * 2);

    #pragma unroll
    for (int mi = 0; mi < 4; mi++) {
        #pragma unroll
        for (int half = 0; half < 2; half++) {
            int gm = m0 + wm * 64 + mi * 16 + g + half * 8;
            int bb_ = gm >> 6, ss_ = gm & 63;
            #pragma unroll
            for (int ni = 0; ni < 4; ni++) {
                int n = nbw + wn * 32 + ni * 8 + t4 * 2;
                float2 v;
                v.x = acc[mi][ni][half * 2 + 0] + bfrag[ni].x;
                v.y = acc[mi][ni][half * 2 + 1] + bfrag[ni].y;
                if (MODE == 0) {
                    int h = n >> 6, d = n & 63;
                    float* dst = g_qkv + (long long)wsel * QKVSTRIDE
                               + (long long)(bb_ * PH + h) * HEADSZ + ss_ * 64 + d;
                    *reinterpret_cast<float2*>(dst) = v;
                } else {
                    float* dst = Cout + ((long long)bb_ * PS + ss_) * PF + n;
                    *reinterpret_cast<float2*>(dst) = v;
                }
            }
        }
    }
}

// ---------------------------------------------------------------------------
// Attention body for one (b,h); smem carved from dynamic buffer.
// ---------------------------------------------------------------------------
__device__ __forceinline__ void attn_body(int b, int h, float* sm) {
    float* sq = sm;
    float* sk = sm + 4096;
    float* ss = sm + 8192;

    const int tid = threadIdx.x;
    const float* qg = g_qkv + (long long)(b * PH + h) * HEADSZ;
    const float* kg = qg + (long long)QKVSTRIDE;
    const float* vg = kg + (long long)QKVSTRIDE;
    const int lane = tid & 31;

    for (int t = tid; t < 1024; t += 256)
        reinterpret_cast<float4*>(sq)[t] = reinterpret_cast<const float4*>(qg)[t];
    for (int t = tid; t < 1024; t += 256) {
        int j = t >> 4, d4 = (t & 15) * 4;
        float4 v = reinterpret_cast<const float4*>(kg)[t];
        *reinterpret_cast<float4*>(&sk[j * 64 + (d4 ^ ((j & 7) << 3))]) = v;
    }
    __syncthreads();

    #pragma unroll
    for (int t = 0; t < 16; t++) {
        int idx = tid + (t << 8);
        int i = idx >> 6, j = idx & 63;
        int sw = (j & 7) << 3;
        float s = 0.f;
        #pragma unroll
        for (int dd = 0; dd < 64; dd += 4) {
            float4 q4 = *reinterpret_cast<const float4*>(&sq[i * 64 + dd]);
            float4 k4 = *reinterpret_cast<const float4*>(&sk[j * 64 + (dd ^ sw)]);
            s += q4.x * k4.x + q4.y * k4.y + q4.z * k4.z + q4.w * k4.w;
        }
        ss[idx] = s * 0.125f;
    }
    __syncthreads();

    {
        int w = tid >> 5;
        #pragma unroll
        for (int rr = 0; rr < 8; rr++) {
            int i = w * 8 + rr;
            float x0 = ss[i * 64 + lane];
            float x1 = ss[i * 64 + 32 + lane];
            float m = fmaxf(x0, x1);
            #pragma unroll
            for (int o = 16; o; o >>= 1) m = fmaxf(m, __shfl_xor_sync(0xffffffffu, m, o));
            float e0 = __expf(x0 - m), e1 = __expf(x1 - m);
            float sum = e0 + e1;
            #pragma unroll
            for (int o = 16; o; o >>= 1) sum += __shfl_xor_sync(0xffffffffu, sum, o);
            float inv = 1.0f / sum;
            ss[i * 64 + lane]      = e0 * inv;
            ss[i * 64 + 32 + lane] = e1 * inv;
        }
    }
    __syncthreads();

    for (int t = tid; t < 1024; t += 256)
        reinterpret_cast<float4*>(sq)[t] = reinterpret_cast<const float4*>(vg)[t];
    __syncthreads();

    #pragma unroll
    for (int t = 0; t < 4; t++) {
        int gidx = tid + (t << 8);
        int i  = gidx >> 4;
        int d4 = (gidx & 15) * 4;
        float ox = 0.f, oy = 0.f, oz = 0.f, ow = 0.f;
        #pragma unroll 16
        for (int j = 0; j < 64; j++) {
            float a = ss[i * 64 + j];
            float4 v4 = *reinterpret_cast<const float4*>(&sq[j * 64 + d4]);
            ox += a * v4.x; oy += a * v4.y; oz += a * v4.z; ow += a * v4.w;
        }
        float4 o4; o4.x = ox; o4.y = oy; o4.z = oz; o4.w = ow;
        *reinterpret_cast<float4*>(&g_o[(long long)(b * 64 + i) * PF + h * 64 + d4]) = o4;
    }
}

// ---------------------------------------------------------------------------
// Mega kernel: [0,576) gemm0+copy, [576,1344) attention, [1344,1536) gemm1.
// Cross-phase deps via g_sync flags; every block waits only on lower-indexed
// blocks (in-order dispatch => deadlock-free).
// ---------------------------------------------------------------------------
__global__ void __launch_bounds__(256, 2) mega_kernel(
    const float* __restrict__ x,
    const float* __restrict__ Wq, const float* __restrict__ bq,
    const float* __restrict__ Wk, const float* __restrict__ bk,
    const float* __restrict__ Wv, const float* __restrict__ bv,
    const float* __restrict__ Wo, const float* __restrict__ bo,
    float* __restrict__ out)
{
    extern __shared__ float sm[];
    const int bid = blockIdx.x;
    const int tid = threadIdx.x;

    if (bid < 576) {
        gemm_body<0>(bid & 31, bid >> 5, sm, x, Wq, Wk, Wv, bq, bk, bv, out);
        __threadfence();
        __syncthreads();
        if (tid == 0) atomicExch(&g_sync[bid], 1);
        return;
    }

    if (bid < 1344) {
        int idx = bid - 576;
        int b = idx / 12, h = idx - (idx / 12) * 12;
        int bx = b >> 1, hp = h >> 1;
        if (tid == 0) {
            wait_flag(&g_sync[(0 * 6 + hp) * 32 + bx], 1);   // Q tile
            wait_flag(&g_sync[(1 * 6 + hp) * 32 + bx], 1);   // K tile
            wait_flag(&g_sync[(2 * 6 + hp) * 32 + bx], 1);   // V tile
            __threadfence();
        }
        __syncthreads();
        attn_body(b, h, sm);
        __threadfence();
        __syncthreads();
        if (tid == 0) atomicAdd(&g_sync[576 + bx], 1);
        return;
    }

    {
        int t = bid - 1344;
        int bx = t & 31, ny = t >> 5;
        if (tid == 0) {
            wait_flag(&g_sync[576 + bx], 24);                // both batches, all heads
            __threadfence();
        }
        __syncthreads();
        gemm_body<1>(bx, ny, sm, nullptr, Wo, nullptr, nullptr,
                     bo, nullptr, nullptr, out);
    }
}

// ---------------------------------------------------------------------------
extern "C" void kernel_launch(void* const* d_in, const int* in_sizes, int n_in,
                              void* d_out, int out_size) {
    const float* x  = (const float*)d_in[0];
    const float* Wq = (const float*)d_in[1];
    const float* bq = (const float*)d_in[2];
    const float* Wk = (const float*)d_in[3];
    const float* bk = (const float*)d_in[4];
    const float* Wv = (const float*)d_in[5];
    const float* bv = (const float*)d_in[6];
    const float* Wo = (const float*)d_in[7];
    const float* bo = (const float*)d_in[8];
    float* out = (float*)d_out;

    cudaFuncSetAttribute(mega_kernel, cudaFuncAttributeMaxDynamicSharedMemorySize, DSMEM);

    // Reset cross-phase flags (graph-capturable memset node, replay-safe)
    void* sync_ptr = nullptr;
    cudaGetSymbolAddress(&sync_ptr, g_sync);
    cudaMemsetAsync(sync_ptr, 0, 608 * sizeof(int));

    mega_kernel<<<1536, 256, DSMEM>>>(x, Wq, bq, Wk, bk, Wv, bv, Wo, bo, out);
}